// round 5
// baseline (speedup 1.0000x reference)
#include <cuda_runtime.h>
#include <cstdint>

// ============================================================================
// ForexLSTM: 2-layer LSTM (B=512, T=1024, H=65) + final linear.
//
// R3:
//  - pre_kernel: pre[b,t,g] = bias + x·W_ih^T. 8 rows/iter (8 indep accums).
//  - recur_kernel: gate->lane remap so the 4 gates of hidden unit j live in
//    one lane-quad; 3 shfl + in-register cell state; double-buffered h_sm;
//    ONE __syncthreads per step.
// ============================================================================

using u32 = unsigned int;
using ull = unsigned long long;

constexpr int B = 512, T = 1024, H = 65, G4 = 260;
constexpr int PTHR = 288, PGRID = 296;
constexpr int GROUPS8 = (B * T) / 8;     // 65536 groups of 8 rows
constexpr int RTHR = 544, RGRID = 128;

__device__ float g_pre[(size_t)B * T * G4];   // 545 MB scratch
__device__ float g_h1 [(size_t)B * T * H];    // layer-0 output sequence
__device__ float g_hN [B * H];                // layer-1 last-step h

// ---------------- packed f32x2 helpers ----------------
__device__ __forceinline__ ull pack2(float x, float y) {
    ull r; asm("mov.b64 %0, {%1, %2};" : "=l"(r) : "f"(x), "f"(y)); return r;
}
__device__ __forceinline__ float2 unpack2(ull v) {
    float2 r; asm("mov.b64 {%0, %1}, %2;" : "=f"(r.x), "=f"(r.y) : "l"(v)); return r;
}
__device__ __forceinline__ void fma2(ull& d, ull a, ull b) {
    asm("fma.rn.f32x2 %0, %1, %2, %0;" : "+l"(d) : "l"(a), "l"(b));
}
__device__ __forceinline__ void lds128(ull& a, ull& b, u32 addr) {
    asm volatile("ld.shared.v2.u64 {%0, %1}, [%2];" : "=l"(a), "=l"(b) : "r"(addr));
}
__device__ __forceinline__ ull lds64(u32 addr) {
    ull a; asm volatile("ld.shared.u64 %0, [%1];" : "=l"(a) : "r"(addr)); return a;
}
__device__ __forceinline__ float fast_tanh(float v) {
    return 1.0f - 2.0f * __fdividef(1.0f, __expf(2.0f * v) + 1.0f);
}

// ============================================================================
// pre[row, g] = (b_ih[g]+b_hh[g]) + sum_i xin[row,i] * w_ih[g,i]
// 8 rows per iteration, 8 independent f32x2 accumulators per thread.
// ============================================================================
__global__ void __launch_bounds__(PTHR, 2)
pre_kernel(const float* __restrict__ x_ext,
           const float* __restrict__ w_ih,
           const float* __restrict__ b_ih,
           const float* __restrict__ b_hh,
           int layer)
{
    const float* xin = (layer == 0) ? x_ext : g_h1;

    __shared__ __align__(16) float xs[2][8 * 68];
    const int tid = threadIdx.x;
    const bool act = tid < G4;

    ull wih[33]; float bg = 0.f;
    if (act) {
        const float* wi = w_ih + tid * H;
#pragma unroll
        for (int j = 0; j < 32; j++)
            wih[j] = pack2(__ldg(wi + 2 * j), __ldg(wi + 2 * j + 1));
        wih[32] = pack2(__ldg(wi + 64), 0.f);
        bg = __ldg(b_ih + tid) + __ldg(b_hh + tid);
    }
    for (int k = tid; k < 2 * 8 * 68; k += PTHR) (&xs[0][0])[k] = 0.f;
    __syncthreads();

    // staging: group of 8 rows = 520 contiguous floats; thread loads 2
    const int f0 = tid, f1 = tid + 260;
    const int s0 = (f0 / 65) * 68 + (f0 % 65);
    const int s1 = (f1 / 65) * 68 + (f1 % 65);

    int gi = blockIdx.x;
    if (act) {
        const float* src = xin + (size_t)gi * 520;
        xs[0][s0] = __ldg(src + f0);
        xs[0][s1] = __ldg(src + f1);
    }
    __syncthreads();

    const u32 xb = (u32)__cvta_generic_to_shared(&xs[0][0]);
    int cur = 0;
    for (; gi < GROUPS8; gi += PGRID) {
        const int gn = gi + PGRID;
        float xn0 = 0.f, xn1 = 0.f;
        if (act && gn < GROUPS8) {
            const float* src = xin + (size_t)gn * 520;
            xn0 = __ldg(src + f0);
            xn1 = __ldg(src + f1);
        }

        if (act) {
            ull a[8];
#pragma unroll
            for (int r = 0; r < 8; r++) a[r] = pack2(bg, 0.f);
            const u32 bA = xb + cur * (8 * 68 * 4);
#pragma unroll
            for (int q = 0; q < 16; q++) {
#pragma unroll
                for (int r = 0; r < 8; r++) {
                    ull u0, u1;
                    lds128(u0, u1, bA + r * 272 + q * 16);
                    fma2(a[r], wih[2 * q], u0);
                    fma2(a[r], wih[2 * q + 1], u1);
                }
            }
#pragma unroll
            for (int r = 0; r < 8; r++)
                fma2(a[r], wih[32], lds64(bA + r * 272 + 256));

            float* op = g_pre + ((size_t)gi * 8) * G4 + tid;
#pragma unroll
            for (int r = 0; r < 8; r++) {
                float2 s = unpack2(a[r]);
                op[(size_t)r * G4] = s.x + s.y;
            }
        }
        if (act && gn < GROUPS8) {
            xs[cur ^ 1][s0] = xn0;
            xs[cur ^ 1][s1] = xn1;
        }
        __syncthreads();
        cur ^= 1;
    }
}

// ============================================================================
// Recurrent kernel: gates = pre[t] + h·W_hh^T, cell update in-register.
// 128 CTAs × 4 rows, 544 threads (520 active).
// tid = r01*260 + j*4 + gsel ; thread handles rows {r01, r01+2}, gate gsel*65+j.
// Lane-quad holds the 4 gates of unit j -> 3 shfl, lane gsel==0 owns c.
// ============================================================================
__global__ void __launch_bounds__(RTHR, 1)
recur_kernel(const float* __restrict__ w_hh, int write_all)
{
    __shared__ __align__(16) float h_sm[2][4 * 68];

    const int tid = threadIdx.x;
    const int b0  = blockIdx.x * 4;
    const bool gact = tid < 520;

    const int r01  = tid / 260;          // 0/1
    const int q    = tid % 260;
    const int j    = q >> 2;             // hidden unit
    const int gsel = q & 3;              // 0=i 1=f 2=g 3=o
    const int g    = gsel * 65 + j;      // gate row in W_hh / pre
    const int rA   = r01, rB = r01 + 2;  // CTA-local rows

    const unsigned mask = (tid >= 512) ? 0xffu : 0xffffffffu;
    const int lane = tid & 31;
    const int lbase = lane & ~3;

    ull whh[33];
    if (gact) {
        const float* wh = w_hh + g * H;
#pragma unroll
        for (int k = 0; k < 32; k++)
            whh[k] = pack2(__ldg(wh + 2 * k), __ldg(wh + 2 * k + 1));
        whh[32] = pack2(__ldg(wh + 64), 0.f);
    }

    const float* pA = g_pre + ((size_t)(b0 + rA) * T) * G4 + g;
    const float* pB = g_pre + ((size_t)(b0 + rB) * T) * G4 + g;

    for (int k = tid; k < 2 * 4 * 68; k += RTHR) (&h_sm[0][0])[k] = 0.f;
    __syncthreads();

    const u32 hb = (u32)__cvta_generic_to_shared(&h_sm[0][0]);
    const bool is_t = (gsel == 2);

    float cA = 0.f, cB = 0.f;
    float pvA = 0.f, pvB = 0.f;
    if (gact) { pvA = __ldg(pA); pvB = __ldg(pB); }

    for (int t = 0; t < T; t++) {
        const int cur = t & 1;

        float pnA = 0.f, pnB = 0.f;
        if (gact && t + 1 < T) {
            pnA = __ldg(pA + (size_t)(t + 1) * G4);
            pnB = __ldg(pB + (size_t)(t + 1) * G4);
        }

        if (gact) {
            // ---- matvec: two independent 17-deep chains per row ----
            ull aA0 = 0ull, aA1 = 0ull, aB0 = 0ull, aB1 = 0ull;
            const u32 hA = hb + cur * 1088 + rA * 272;
            const u32 hB = hb + cur * 1088 + rB * 272;
#pragma unroll
            for (int k = 0; k < 8; k++) {
                ull u0, u1, v0, v1;
                lds128(u0, u1, hA + k * 32);
                lds128(v0, v1, hB + k * 32);
                fma2(aA0, whh[4 * k],     u0); fma2(aA1, whh[4 * k + 1], u1);
                fma2(aB0, whh[4 * k],     v0); fma2(aB1, whh[4 * k + 1], v1);
                lds128(u0, u1, hA + k * 32 + 16);
                lds128(v0, v1, hB + k * 32 + 16);
                fma2(aA0, whh[4 * k + 2], u0); fma2(aA1, whh[4 * k + 3], u1);
                fma2(aB0, whh[4 * k + 2], v0); fma2(aB1, whh[4 * k + 3], v1);
            }
            fma2(aA0, whh[32], lds64(hA + 256));
            fma2(aB0, whh[32], lds64(hB + 256));

            float2 sA0 = unpack2(aA0), sA1 = unpack2(aA1);
            float2 sB0 = unpack2(aB0), sB1 = unpack2(aB1);
            float vA = ((sA0.x + sA0.y) + (sA1.x + sA1.y)) + pvA;
            float vB = ((sB0.x + sB0.y) + (sB1.x + sB1.y)) + pvB;

            // i/f/o -> sigmoid ; g -> tanh = 2*sigmoid(2v)-1 (branch-free)
            float zA = is_t ? 2.f * vA : vA;
            float zB = is_t ? 2.f * vB : vB;
            float sgA = __fdividef(1.f, 1.f + __expf(-zA));
            float sgB = __fdividef(1.f, 1.f + __expf(-zB));
            float aAv = is_t ? (2.f * sgA - 1.f) : sgA;
            float aBv = is_t ? (2.f * sgB - 1.f) : sgB;

            // ---- quad exchange: lane gsel==0 collects i,f,g,o ----
            float fAv = __shfl_sync(mask, aAv, lbase + 1);
            float gAv = __shfl_sync(mask, aAv, lbase + 2);
            float oAv = __shfl_sync(mask, aAv, lbase + 3);
            float fBv = __shfl_sync(mask, aBv, lbase + 1);
            float gBv = __shfl_sync(mask, aBv, lbase + 2);
            float oBv = __shfl_sync(mask, aBv, lbase + 3);

            if (gsel == 0) {
                cA = fAv * cA + aAv * gAv;
                cB = fBv * cB + aBv * gBv;
                float hAv = oAv * fast_tanh(cA);
                float hBv = oBv * fast_tanh(cB);
                float* nb = &h_sm[cur ^ 1][0];
                nb[rA * 68 + j] = hAv;
                nb[rB * 68 + j] = hBv;
                if (write_all) {
                    g_h1[((size_t)(b0 + rA) * T + t) * H + j] = hAv;
                    g_h1[((size_t)(b0 + rB) * T + t) * H + j] = hBv;
                } else if (t == T - 1) {
                    g_hN[(size_t)(b0 + rA) * H + j] = hAv;
                    g_hN[(size_t)(b0 + rB) * H + j] = hBv;
                }
            }
        }
        pvA = pnA; pvB = pnB;
        __syncthreads();
    }
}

// ============================================================================
// out[b] = g_hN[b,:] . w_lin + b_lin
// ============================================================================
__global__ void final_linear_kernel(const float* __restrict__ w_lin,
                                    const float* __restrict__ b_lin,
                                    float* __restrict__ out)
{
    __shared__ float w[72];
    const int tid = threadIdx.x;
    if (tid < H) w[tid] = __ldg(w_lin + tid);
    __syncthreads();
    const int b = blockIdx.x * blockDim.x + tid;
    if (b < B) {
        const float* h = g_hN + (size_t)b * H;
        float s = __ldg(b_lin);
#pragma unroll
        for (int i = 0; i < H; i++) s += h[i] * w[i];
        out[b] = s;
    }
}

// ============================================================================
extern "C" void kernel_launch(void* const* d_in, const int* in_sizes, int n_in,
                              void* d_out, int out_size)
{
    const float* x     = (const float*)d_in[0];
    const float* w_ih0 = (const float*)d_in[1];
    const float* w_hh0 = (const float*)d_in[2];
    const float* b_ih0 = (const float*)d_in[3];
    const float* b_hh0 = (const float*)d_in[4];
    const float* w_ih1 = (const float*)d_in[5];
    const float* w_hh1 = (const float*)d_in[6];
    const float* b_ih1 = (const float*)d_in[7];
    const float* b_hh1 = (const float*)d_in[8];
    const float* w_lin = (const float*)d_in[9];
    const float* b_lin = (const float*)d_in[10];

    pre_kernel<<<PGRID, PTHR>>>(x, w_ih0, b_ih0, b_hh0, 0);
    recur_kernel<<<RGRID, RTHR>>>(w_hh0, 1);
    pre_kernel<<<PGRID, PTHR>>>(x, w_ih1, b_ih1, b_hh1, 1);
    recur_kernel<<<RGRID, RTHR>>>(w_hh1, 0);
    final_linear_kernel<<<2, 256>>>(w_lin, b_lin, (float*)d_out);
}

// round 8
// speedup vs baseline: 1.6650x; 1.6650x over previous
#include <cuda_runtime.h>
#include <cstdint>

// ============================================================================
// ForexLSTM: 2-layer LSTM (B=512, T=1024, H=65) + final linear.
//
// R7 (de-risked R5):
//  - pre_kernel: 8-row double-buffered tiles (2 sub-blocks x 4 rows,
//    4 accumulators -> no spills), ONE barrier per 8 rows.
//  - recur_kernel: 256 CTAs x 2 rows, 2 CTAs/SM. Gates through smem,
//    two barriers/step; per-barrier group is 9 warps and the two resident
//    CTAs overlap each other's barrier bubbles.
// ============================================================================

using u32 = unsigned int;
using ull = unsigned long long;

constexpr int B = 512, T = 1024, H = 65, G4 = 260;
constexpr int PTHR = 288, PGRID = 296;
constexpr int TILE = 8;                       // rows per pre tile
constexpr int NTILES = (B * T) / TILE;        // 65536
constexpr int RTHR = 288, RGRID = 256;        // 2 rows per CTA

__device__ float g_pre[(size_t)B * T * G4];   // 545 MB scratch
__device__ float g_h1 [(size_t)B * T * H];    // layer-0 output sequence
__device__ float g_hN [B * H];                // layer-1 last-step h

// ---------------- packed f32x2 helpers ----------------
__device__ __forceinline__ ull pack2(float x, float y) {
    ull r; asm("mov.b64 %0, {%1, %2};" : "=l"(r) : "f"(x), "f"(y)); return r;
}
__device__ __forceinline__ float2 unpack2(ull v) {
    float2 r; asm("mov.b64 {%0, %1}, %2;" : "=f"(r.x), "=f"(r.y) : "l"(v)); return r;
}
__device__ __forceinline__ void fma2(ull& d, ull a, ull b) {
    asm("fma.rn.f32x2 %0, %1, %2, %0;" : "+l"(d) : "l"(a), "l"(b));
}
__device__ __forceinline__ void lds128(ull& a, ull& b, u32 addr) {
    asm volatile("ld.shared.v2.u64 {%0, %1}, [%2];" : "=l"(a), "=l"(b) : "r"(addr));
}
__device__ __forceinline__ ull lds64(u32 addr) {
    ull a; asm volatile("ld.shared.u64 %0, [%1];" : "=l"(a) : "r"(addr)); return a;
}
__device__ __forceinline__ float fast_tanh(float v) {
    return 1.0f - 2.0f * __fdividef(1.0f, __expf(2.0f * v) + 1.0f);
}

// ============================================================================
// pre[row, g] = (b_ih[g]+b_hh[g]) + sum_i xin[row,i] * w_ih[g,i]
// 8-row tiles, double-buffered; one __syncthreads per tile.
// ============================================================================
__global__ void __launch_bounds__(PTHR, 2)
pre_kernel(const float* __restrict__ x_ext,
           const float* __restrict__ w_ih,
           const float* __restrict__ b_ih,
           const float* __restrict__ b_hh,
           int layer)
{
    const float* xin = (layer == 0) ? x_ext : g_h1;

    __shared__ __align__(16) float xs[2][TILE * 68];
    const int tid = threadIdx.x;
    const bool act = tid < G4;

    ull wih[33]; float bg = 0.f;
    if (act) {
        const float* wi = w_ih + tid * H;
#pragma unroll
        for (int j = 0; j < 32; j++)
            wih[j] = pack2(__ldg(wi + 2 * j), __ldg(wi + 2 * j + 1));
        wih[32] = pack2(__ldg(wi + 64), 0.f);
        bg = __ldg(b_ih + tid) + __ldg(b_hh + tid);
    }
    for (int k = tid; k < 2 * TILE * 68; k += PTHR) (&xs[0][0])[k] = 0.f;
    __syncthreads();

    // staging: tile = 8 rows = 520 contiguous floats; thread loads 2
    const int f0 = tid, f1 = tid + 260;
    const int s0 = (f0 / 65) * 68 + (f0 % 65);
    const int s1 = (f1 / 65) * 68 + (f1 % 65);

    int gi = blockIdx.x;
    if (act) {
        const float* src = xin + (size_t)gi * (TILE * H);
        xs[0][s0] = __ldg(src + f0);
        xs[0][s1] = __ldg(src + f1);
    }
    __syncthreads();

    const u32 xb = (u32)__cvta_generic_to_shared(&xs[0][0]);
    int cur = 0;
    for (; gi < NTILES; gi += PGRID) {
        const int gn = gi + PGRID;
        float xn0 = 0.f, xn1 = 0.f;
        if (act && gn < NTILES) {
            const float* src = xin + (size_t)gn * (TILE * H);
            xn0 = __ldg(src + f0);
            xn1 = __ldg(src + f1);
        }

        if (act) {
            const u32 bT = xb + cur * (TILE * 68 * 4);
#pragma unroll
            for (int sb = 0; sb < 2; sb++) {
                ull a0 = pack2(bg, 0.f), a1 = a0, a2 = a0, a3 = a0;
                const u32 bA = bT + sb * (4 * 272);
#pragma unroll
                for (int q = 0; q < 16; q++) {
                    ull u0, u1;
                    lds128(u0, u1, bA + 0 * 272 + q * 16);
                    fma2(a0, wih[2 * q], u0); fma2(a0, wih[2 * q + 1], u1);
                    lds128(u0, u1, bA + 1 * 272 + q * 16);
                    fma2(a1, wih[2 * q], u0); fma2(a1, wih[2 * q + 1], u1);
                    lds128(u0, u1, bA + 2 * 272 + q * 16);
                    fma2(a2, wih[2 * q], u0); fma2(a2, wih[2 * q + 1], u1);
                    lds128(u0, u1, bA + 3 * 272 + q * 16);
                    fma2(a3, wih[2 * q], u0); fma2(a3, wih[2 * q + 1], u1);
                }
                fma2(a0, wih[32], lds64(bA + 0 * 272 + 256));
                fma2(a1, wih[32], lds64(bA + 1 * 272 + 256));
                fma2(a2, wih[32], lds64(bA + 2 * 272 + 256));
                fma2(a3, wih[32], lds64(bA + 3 * 272 + 256));

                float* op = g_pre + ((size_t)gi * TILE + sb * 4) * G4 + tid;
                float2 s;
                s = unpack2(a0); op[0]      = s.x + s.y;
                s = unpack2(a1); op[G4]     = s.x + s.y;
                s = unpack2(a2); op[2 * G4] = s.x + s.y;
                s = unpack2(a3); op[3 * G4] = s.x + s.y;
            }
        }
        if (act && gn < NTILES) {
            xs[cur ^ 1][s0] = xn0;
            xs[cur ^ 1][s1] = xn1;
        }
        __syncthreads();
        cur ^= 1;
    }
}

// ============================================================================
// Recurrent kernel: gates = pre[t] + h·W_hh^T, LSTM cell update.
// 256 CTAs x 2 rows; 288 threads (260 gate-active, 130 eltwise-active);
// 2 CTAs/SM so barrier bubbles of one CTA are filled by the other.
// ============================================================================
__global__ void __launch_bounds__(RTHR, 2)
recur_kernel(const float* __restrict__ w_hh, int write_all)
{
    __shared__ __align__(16) float h_sm[2 * 68];
    __shared__ float gates_sm[2 * G4];

    const int tid = threadIdx.x;
    const int b0  = blockIdx.x * 2;
    const bool gact = tid < G4;
    const int g = tid;

    ull whh[33];
    if (gact) {
        const float* wh = w_hh + g * H;
#pragma unroll
        for (int k = 0; k < 32; k++)
            whh[k] = pack2(__ldg(wh + 2 * k), __ldg(wh + 2 * k + 1));
        whh[32] = pack2(__ldg(wh + 64), 0.f);
    }

    const bool eact = tid < 130;
    const int r_e = tid / H, i_e = tid % H;

    const float* p0 = g_pre + ((size_t)(b0 + 0) * T) * G4 + g;
    const float* p1 = g_pre + ((size_t)(b0 + 1) * T) * G4 + g;
    const int re = eact ? r_e : 0;
    float* op = write_all ? g_h1 + ((size_t)(b0 + re) * T) * H + i_e
                          : g_hN + (size_t)(b0 + re) * H + i_e;

    for (int k = tid; k < 2 * 68; k += RTHR) h_sm[k] = 0.f;
    __syncthreads();

    const u32 hb = (u32)__cvta_generic_to_shared(h_sm);
    const bool is_t = (g >= 130 && g < 195);
    float c = 0.f;
    float pv0 = 0.f, pv1 = 0.f;
    if (gact) { pv0 = __ldg(p0); pv1 = __ldg(p1); }

    for (int t = 0; t < T; t++) {
        float pn0 = 0.f, pn1 = 0.f;
        if (gact && t + 1 < T) {
            pn0 = __ldg(p0 + (size_t)(t + 1) * G4);
            pn1 = __ldg(p1 + (size_t)(t + 1) * G4);
        }

        if (gact) {
            // two rows, 2 independent ~17-deep chains each
            ull a00 = 0ull, a01 = 0ull, a10 = 0ull, a11 = 0ull;
            const u32 hA = hb;
            const u32 hB = hb + 272;
#pragma unroll
            for (int k = 0; k < 8; k++) {
                ull u0, u1, v0, v1;
                lds128(u0, u1, hA + k * 32);
                lds128(v0, v1, hB + k * 32);
                fma2(a00, whh[4 * k],     u0); fma2(a01, whh[4 * k + 1], u1);
                fma2(a10, whh[4 * k],     v0); fma2(a11, whh[4 * k + 1], v1);
                lds128(u0, u1, hA + k * 32 + 16);
                lds128(v0, v1, hB + k * 32 + 16);
                fma2(a00, whh[4 * k + 2], u0); fma2(a01, whh[4 * k + 3], u1);
                fma2(a10, whh[4 * k + 2], v0); fma2(a11, whh[4 * k + 3], v1);
            }
            fma2(a00, whh[32], lds64(hA + 256));
            fma2(a10, whh[32], lds64(hB + 256));

            float2 s00 = unpack2(a00), s01 = unpack2(a01);
            float2 s10 = unpack2(a10), s11 = unpack2(a11);
            float v0 = ((s00.x + s00.y) + (s01.x + s01.y)) + pv0;
            float v1 = ((s10.x + s10.y) + (s11.x + s11.y)) + pv1;

            float z0 = is_t ? 2.f * v0 : v0;
            float z1 = is_t ? 2.f * v1 : v1;
            float sg0 = __fdividef(1.f, 1.f + __expf(-z0));
            float sg1 = __fdividef(1.f, 1.f + __expf(-z1));
            gates_sm[g]      = is_t ? (2.f * sg0 - 1.f) : sg0;
            gates_sm[G4 + g] = is_t ? (2.f * sg1 - 1.f) : sg1;
        }
        __syncthreads();

        if (eact) {
            const float* gr = gates_sm + r_e * G4;
            float iv = gr[i_e];
            float fv = gr[65 + i_e];
            float gv = gr[130 + i_e];
            float ov = gr[195 + i_e];
            c = fv * c + iv * gv;
            float hv = ov * fast_tanh(c);
            h_sm[r_e * 68 + i_e] = hv;
            if (write_all)        op[(size_t)t * H] = hv;
            else if (t == T - 1)  op[0] = hv;
        }
        pv0 = pn0; pv1 = pn1;
        __syncthreads();
    }
}

// ============================================================================
// out[b] = g_hN[b,:] . w_lin + b_lin
// ============================================================================
__global__ void final_linear_kernel(const float* __restrict__ w_lin,
                                    const float* __restrict__ b_lin,
                                    float* __restrict__ out)
{
    __shared__ float w[72];
    const int tid = threadIdx.x;
    if (tid < H) w[tid] = __ldg(w_lin + tid);
    __syncthreads();
    const int b = blockIdx.x * blockDim.x + tid;
    if (b < B) {
        const float* h = g_hN + (size_t)b * H;
        float s = __ldg(b_lin);
#pragma unroll
        for (int i = 0; i < H; i++) s += h[i] * w[i];
        out[b] = s;
    }
}

// ============================================================================
extern "C" void kernel_launch(void* const* d_in, const int* in_sizes, int n_in,
                              void* d_out, int out_size)
{
    const float* x     = (const float*)d_in[0];
    const float* w_ih0 = (const float*)d_in[1];
    const float* w_hh0 = (const float*)d_in[2];
    const float* b_ih0 = (const float*)d_in[3];
    const float* b_hh0 = (const float*)d_in[4];
    const float* w_ih1 = (const float*)d_in[5];
    const float* w_hh1 = (const float*)d_in[6];
    const float* b_ih1 = (const float*)d_in[7];
    const float* b_hh1 = (const float*)d_in[8];
    const float* w_lin = (const float*)d_in[9];
    const float* b_lin = (const float*)d_in[10];

    pre_kernel<<<PGRID, PTHR>>>(x, w_ih0, b_ih0, b_hh0, 0);
    recur_kernel<<<RGRID, RTHR>>>(w_hh0, 1);
    pre_kernel<<<PGRID, PTHR>>>(x, w_ih1, b_ih1, b_hh1, 1);
    recur_kernel<<<RGRID, RTHR>>>(w_hh1, 0);
    final_linear_kernel<<<2, 256>>>(w_lin, b_lin, (float*)d_out);
}

// round 9
// speedup vs baseline: 1.7463x; 1.0488x over previous
#include <cuda_runtime.h>
#include <cstdint>

// ============================================================================
// ForexLSTM: 2-layer LSTM (B=512, T=1024, H=65) + final linear.
//
// R8:
//  - pre_kernel: unchanged from R7 (8-row double-buffered tiles, near FMA floor).
//  - recur_kernel: phase-1 writes RAW gate preactivations with ONE STS.64 per
//    thread (gates laid out [g][row]); all activations (sigmoid/tanh) moved to
//    the eltwise phase; eltwise threads are tid in [130,260) so low warps hit
//    the barrier right after matvec. 256 CTAs x 2 rows, 2 CTAs/SM.
// ============================================================================

using u32 = unsigned int;
using ull = unsigned long long;

constexpr int B = 512, T = 1024, H = 65, G4 = 260;
constexpr int PTHR = 288, PGRID = 296;
constexpr int TILE = 8;                       // rows per pre tile
constexpr int NTILES = (B * T) / TILE;        // 65536
constexpr int RTHR = 288, RGRID = 256;        // 2 rows per CTA

__device__ float g_pre[(size_t)B * T * G4];   // 545 MB scratch
__device__ float g_h1 [(size_t)B * T * H];    // layer-0 output sequence
__device__ float g_hN [B * H];                // layer-1 last-step h

// ---------------- packed f32x2 helpers ----------------
__device__ __forceinline__ ull pack2(float x, float y) {
    ull r; asm("mov.b64 %0, {%1, %2};" : "=l"(r) : "f"(x), "f"(y)); return r;
}
__device__ __forceinline__ float2 unpack2(ull v) {
    float2 r; asm("mov.b64 {%0, %1}, %2;" : "=f"(r.x), "=f"(r.y) : "l"(v)); return r;
}
__device__ __forceinline__ void fma2(ull& d, ull a, ull b) {
    asm("fma.rn.f32x2 %0, %1, %2, %0;" : "+l"(d) : "l"(a), "l"(b));
}
__device__ __forceinline__ void lds128(ull& a, ull& b, u32 addr) {
    asm volatile("ld.shared.v2.u64 {%0, %1}, [%2];" : "=l"(a), "=l"(b) : "r"(addr));
}
__device__ __forceinline__ ull lds64(u32 addr) {
    ull a; asm volatile("ld.shared.u64 %0, [%1];" : "=l"(a) : "r"(addr)); return a;
}
__device__ __forceinline__ void sts64v(u32 addr, float x, float y) {
    asm volatile("st.shared.v2.f32 [%0], {%1, %2};" :: "r"(addr), "f"(x), "f"(y) : "memory");
}
__device__ __forceinline__ float fast_sigmoid(float v) {
    return __fdividef(1.0f, 1.0f + __expf(-v));
}
__device__ __forceinline__ float fast_tanh(float v) {
    return 1.0f - 2.0f * __fdividef(1.0f, __expf(2.0f * v) + 1.0f);
}

// ============================================================================
// pre[row, g] = (b_ih[g]+b_hh[g]) + sum_i xin[row,i] * w_ih[g,i]
// 8-row tiles, double-buffered; one __syncthreads per tile.
// ============================================================================
__global__ void __launch_bounds__(PTHR, 2)
pre_kernel(const float* __restrict__ x_ext,
           const float* __restrict__ w_ih,
           const float* __restrict__ b_ih,
           const float* __restrict__ b_hh,
           int layer)
{
    const float* xin = (layer == 0) ? x_ext : g_h1;

    __shared__ __align__(16) float xs[2][TILE * 68];
    const int tid = threadIdx.x;
    const bool act = tid < G4;

    ull wih[33]; float bg = 0.f;
    if (act) {
        const float* wi = w_ih + tid * H;
#pragma unroll
        for (int j = 0; j < 32; j++)
            wih[j] = pack2(__ldg(wi + 2 * j), __ldg(wi + 2 * j + 1));
        wih[32] = pack2(__ldg(wi + 64), 0.f);
        bg = __ldg(b_ih + tid) + __ldg(b_hh + tid);
    }
    for (int k = tid; k < 2 * TILE * 68; k += PTHR) (&xs[0][0])[k] = 0.f;
    __syncthreads();

    const int f0 = tid, f1 = tid + 260;
    const int s0 = (f0 / 65) * 68 + (f0 % 65);
    const int s1 = (f1 / 65) * 68 + (f1 % 65);

    int gi = blockIdx.x;
    if (act) {
        const float* src = xin + (size_t)gi * (TILE * H);
        xs[0][s0] = __ldg(src + f0);
        xs[0][s1] = __ldg(src + f1);
    }
    __syncthreads();

    const u32 xb = (u32)__cvta_generic_to_shared(&xs[0][0]);
    int cur = 0;
    for (; gi < NTILES; gi += PGRID) {
        const int gn = gi + PGRID;
        float xn0 = 0.f, xn1 = 0.f;
        if (act && gn < NTILES) {
            const float* src = xin + (size_t)gn * (TILE * H);
            xn0 = __ldg(src + f0);
            xn1 = __ldg(src + f1);
        }

        if (act) {
            const u32 bT = xb + cur * (TILE * 68 * 4);
#pragma unroll
            for (int sb = 0; sb < 2; sb++) {
                ull a0 = pack2(bg, 0.f), a1 = a0, a2 = a0, a3 = a0;
                const u32 bA = bT + sb * (4 * 272);
#pragma unroll
                for (int q = 0; q < 16; q++) {
                    ull u0, u1;
                    lds128(u0, u1, bA + 0 * 272 + q * 16);
                    fma2(a0, wih[2 * q], u0); fma2(a0, wih[2 * q + 1], u1);
                    lds128(u0, u1, bA + 1 * 272 + q * 16);
                    fma2(a1, wih[2 * q], u0); fma2(a1, wih[2 * q + 1], u1);
                    lds128(u0, u1, bA + 2 * 272 + q * 16);
                    fma2(a2, wih[2 * q], u0); fma2(a2, wih[2 * q + 1], u1);
                    lds128(u0, u1, bA + 3 * 272 + q * 16);
                    fma2(a3, wih[2 * q], u0); fma2(a3, wih[2 * q + 1], u1);
                }
                fma2(a0, wih[32], lds64(bA + 0 * 272 + 256));
                fma2(a1, wih[32], lds64(bA + 1 * 272 + 256));
                fma2(a2, wih[32], lds64(bA + 2 * 272 + 256));
                fma2(a3, wih[32], lds64(bA + 3 * 272 + 256));

                float* op = g_pre + ((size_t)gi * TILE + sb * 4) * G4 + tid;
                float2 s;
                s = unpack2(a0); op[0]      = s.x + s.y;
                s = unpack2(a1); op[G4]     = s.x + s.y;
                s = unpack2(a2); op[2 * G4] = s.x + s.y;
                s = unpack2(a3); op[3 * G4] = s.x + s.y;
            }
        }
        if (act && gn < NTILES) {
            xs[cur ^ 1][s0] = xn0;
            xs[cur ^ 1][s1] = xn1;
        }
        __syncthreads();
        cur ^= 1;
    }
}

// ============================================================================
// Recurrent kernel: gates = pre[t] + h·W_hh^T (raw), then eltwise applies
// activations + cell update. 256 CTAs x 2 rows, 2 CTAs/SM.
// gates layout: [g][row] pairs -> ONE STS.64 per gate thread per step.
// ============================================================================
__global__ void __launch_bounds__(RTHR, 2)
recur_kernel(const float* __restrict__ w_hh, int write_all)
{
    __shared__ __align__(16) float h_sm[2 * 68];
    __shared__ __align__(8)  float gates_sm[G4 * 2];   // [g][row]

    const int tid = threadIdx.x;
    const int b0  = blockIdx.x * 2;
    const bool gact = tid < G4;
    const int g = tid;

    ull whh[33];
    if (gact) {
        const float* wh = w_hh + g * H;
#pragma unroll
        for (int k = 0; k < 32; k++)
            whh[k] = pack2(__ldg(wh + 2 * k), __ldg(wh + 2 * k + 1));
        whh[32] = pack2(__ldg(wh + 64), 0.f);
    }

    // eltwise threads: tid in [130,260) -> warps 4..8 (warps 0-3 idle in ph2)
    const int et = tid - 130;
    const bool eact = (et >= 0) && (et < 130);
    const int r_e = eact ? (et / H) : 0;
    const int i_e = eact ? (et % H) : 0;

    const float* p0 = g_pre + ((size_t)(b0 + 0) * T) * G4 + g;
    const float* p1 = g_pre + ((size_t)(b0 + 1) * T) * G4 + g;
    float* op = write_all ? g_h1 + ((size_t)(b0 + r_e) * T) * H + i_e
                          : g_hN + (size_t)(b0 + r_e) * H + i_e;

    for (int k = tid; k < 2 * 68; k += RTHR) h_sm[k] = 0.f;
    __syncthreads();

    const u32 hb = (u32)__cvta_generic_to_shared(h_sm);
    const u32 gb = (u32)__cvta_generic_to_shared(gates_sm);
    float c = 0.f;
    float pv0 = 0.f, pv1 = 0.f;
    if (gact) { pv0 = __ldg(p0); pv1 = __ldg(p1); }

    for (int t = 0; t < T; t++) {
        float pn0 = 0.f, pn1 = 0.f;
        if (gact && t + 1 < T) {
            pn0 = __ldg(p0 + (size_t)(t + 1) * G4);
            pn1 = __ldg(p1 + (size_t)(t + 1) * G4);
        }

        if (gact) {
            // two rows, 2 independent ~17-deep chains each
            ull a00 = 0ull, a01 = 0ull, a10 = 0ull, a11 = 0ull;
            const u32 hA = hb;
            const u32 hB = hb + 272;
#pragma unroll
            for (int k = 0; k < 8; k++) {
                ull u0, u1, v0, v1;
                lds128(u0, u1, hA + k * 32);
                lds128(v0, v1, hB + k * 32);
                fma2(a00, whh[4 * k],     u0); fma2(a01, whh[4 * k + 1], u1);
                fma2(a10, whh[4 * k],     v0); fma2(a11, whh[4 * k + 1], v1);
                lds128(u0, u1, hA + k * 32 + 16);
                lds128(v0, v1, hB + k * 32 + 16);
                fma2(a00, whh[4 * k + 2], u0); fma2(a01, whh[4 * k + 3], u1);
                fma2(a10, whh[4 * k + 2], v0); fma2(a11, whh[4 * k + 3], v1);
            }
            fma2(a00, whh[32], lds64(hA + 256));
            fma2(a10, whh[32], lds64(hB + 256));

            float2 s00 = unpack2(a00), s01 = unpack2(a01);
            float2 s10 = unpack2(a10), s11 = unpack2(a11);
            float v0 = ((s00.x + s00.y) + (s01.x + s01.y)) + pv0;
            float v1 = ((s10.x + s10.y) + (s11.x + s11.y)) + pv1;

            // RAW preactivations, single wide store (no MUFU in this phase)
            sts64v(gb + g * 8, v0, v1);
        }
        __syncthreads();

        if (eact) {
            // gates_sm[g*2 + row]
            const u32 ga = gb + r_e * 4;
            float vi, vf, vg, vo;
            asm volatile("ld.shared.f32 %0, [%1];" : "=f"(vi) : "r"(ga + (i_e)       * 8));
            asm volatile("ld.shared.f32 %0, [%1];" : "=f"(vf) : "r"(ga + (65 + i_e)  * 8));
            asm volatile("ld.shared.f32 %0, [%1];" : "=f"(vg) : "r"(ga + (130 + i_e) * 8));
            asm volatile("ld.shared.f32 %0, [%1];" : "=f"(vo) : "r"(ga + (195 + i_e) * 8));
            float iv = fast_sigmoid(vi);
            float fv = fast_sigmoid(vf);
            float gv = fast_tanh(vg);
            float ov = fast_sigmoid(vo);
            c = fv * c + iv * gv;
            float hv = ov * fast_tanh(c);
            h_sm[r_e * 68 + i_e] = hv;
            if (write_all)        op[(size_t)t * H] = hv;
            else if (t == T - 1)  op[0] = hv;
        }
        pv0 = pn0; pv1 = pn1;
        __syncthreads();
    }
}

// ============================================================================
// out[b] = g_hN[b,:] . w_lin + b_lin
// ============================================================================
__global__ void final_linear_kernel(const float* __restrict__ w_lin,
                                    const float* __restrict__ b_lin,
                                    float* __restrict__ out)
{
    __shared__ float w[72];
    const int tid = threadIdx.x;
    if (tid < H) w[tid] = __ldg(w_lin + tid);
    __syncthreads();
    const int b = blockIdx.x * blockDim.x + tid;
    if (b < B) {
        const float* h = g_hN + (size_t)b * H;
        float s = __ldg(b_lin);
#pragma unroll
        for (int i = 0; i < H; i++) s += h[i] * w[i];
        out[b] = s;
    }
}

// ============================================================================
extern "C" void kernel_launch(void* const* d_in, const int* in_sizes, int n_in,
                              void* d_out, int out_size)
{
    const float* x     = (const float*)d_in[0];
    const float* w_ih0 = (const float*)d_in[1];
    const float* w_hh0 = (const float*)d_in[2];
    const float* b_ih0 = (const float*)d_in[3];
    const float* b_hh0 = (const float*)d_in[4];
    const float* w_ih1 = (const float*)d_in[5];
    const float* w_hh1 = (const float*)d_in[6];
    const float* b_ih1 = (const float*)d_in[7];
    const float* b_hh1 = (const float*)d_in[8];
    const float* w_lin = (const float*)d_in[9];
    const float* b_lin = (const float*)d_in[10];

    pre_kernel<<<PGRID, PTHR>>>(x, w_ih0, b_ih0, b_hh0, 0);
    recur_kernel<<<RGRID, RTHR>>>(w_hh0, 1);
    pre_kernel<<<PGRID, PTHR>>>(x, w_ih1, b_ih1, b_hh1, 1);
    recur_kernel<<<RGRID, RTHR>>>(w_hh1, 0);
    final_linear_kernel<<<2, 256>>>(w_lin, b_lin, (float*)d_out);
}